// round 14
// baseline (speedup 1.0000x reference)
#include <cuda_runtime.h>
#include <cuda_fp16.h>
#include <cstdint>
#include <math.h>

#define S_LEN 2048
#define D_MOD 1024
#define ROWS  4096          // B*S
#define NBH   32            // B*H
#define QSCALE 0.18033688011112042f   // 0.125 * log2(e)
#define POFF   8.0f                   // fixed exp2-domain offset (cancels in O/l)
#define ONES2  0x3C003C00u            // half2(1,1)

// ---------------- scratch (static; no allocations) ----------
__device__ __align__(128) __half g_xh [ROWS * D_MOD];
__device__ __align__(128) __half g_Wh [3 * D_MOD * D_MOD];    // [3072][1024] K-major fp16
__device__ __align__(128) __half g_Woh[D_MOD * D_MOD];
__device__ __align__(128) __half g_Q  [NBH * S_LEN * 64];     // pre-scaled by QSCALE
__device__ __align__(128) __half g_K  [NBH * S_LEN * 64];
__device__ __align__(128) __half g_Vt [NBH * 64 * S_LEN];     // [bh][dk][s] (written by GEMM)
__device__ __align__(128) __half g_ctxh[ROWS * D_MOD];
__device__ __align__(128) float  g_prj[ROWS * D_MOD];         // x + ctx@Wo + bo

// ---------------- helpers ----------------
__device__ __forceinline__ uint32_t smem_u32(const void* p) {
    uint32_t a;
    asm("{ .reg .u64 t; cvta.to.shared.u64 t, %1; cvt.u32.u64 %0, t; }" : "=r"(a) : "l"(p));
    return a;
}
__device__ __forceinline__ void cp16(uint32_t dst, const void* src) {
    asm volatile("cp.async.cg.shared.global [%0], [%1], 16;" :: "r"(dst), "l"(src) : "memory");
}
#define CP_COMMIT() asm volatile("cp.async.commit_group;" ::: "memory")
#define CP_WAIT0()  asm volatile("cp.async.wait_group 0;" ::: "memory")
#define CP_WAIT1()  asm volatile("cp.async.wait_group 1;" ::: "memory")

// p = exp2(half2(a, b)) — POFF already folded into the MMA accumulator init
__device__ __forceinline__ uint32_t pexp2(float a, float b) {
    __half2 h = __floats2half2_rn(a, b);
    uint32_t u = *reinterpret_cast<uint32_t*>(&h);
    uint32_t r;
    asm("ex2.approx.f16x2 %0, %1;" : "=r"(r) : "r"(u));
    return r;
}
__device__ __forceinline__ void mma16(float* d, const uint32_t* a, uint32_t b0, uint32_t b1) {
    asm volatile("mma.sync.aligned.m16n8k16.row.col.f32.f16.f16.f32 "
        "{%0,%1,%2,%3}, {%4,%5,%6,%7}, {%8,%9}, {%0,%1,%2,%3};"
        : "+f"(d[0]), "+f"(d[1]), "+f"(d[2]), "+f"(d[3])
        : "r"(a[0]), "r"(a[1]), "r"(a[2]), "r"(a[3]), "r"(b0), "r"(b1));
}
__device__ __forceinline__ void ldsm4(uint32_t& r0, uint32_t& r1, uint32_t& r2, uint32_t& r3,
                                      uint32_t addr) {
    asm volatile("ldmatrix.sync.aligned.m8n8.x4.shared.b16 {%0,%1,%2,%3}, [%4];"
        : "=r"(r0), "=r"(r1), "=r"(r2), "=r"(r3) : "r"(addr));
}

// ======================= fp16 mma.sync GEMM (256x128 tile, 64x64/warp) =====
// C[4096, N] = A[4096,1024] @ W[N,1024]^T + bias.  BM=256, BN=128, BK=32.
// 8 warps: wm = wid>>1 (0..3, 64 M-rows each), wn = wid&1 (0..1, 64 N-cols).
// QKV=1: Q/K written [B,H,S,64] (Q pre-scaled); V written TRANSPOSED.
// QKV=0: writes float prj = acc + bias + x (residual fused).
#define GPAD 20
#define ASTAGE_B (256 * GPAD * 4)              // 20480 B
#define BSTAGE_B (128 * GPAD * 4)              // 10240 B
#define STAGE_B  (ASTAGE_B + BSTAGE_B)         // 30720 B
#define GEMM_SMEM (3 * STAGE_B)                // 92160 B

template <int QKV>
__global__ __launch_bounds__(256, 1) void gemm_h(
    const __half* __restrict__ A, const __half* __restrict__ W,
    const float* __restrict__ b0, const float* __restrict__ b1, const float* __restrict__ b2,
    __half* __restrict__ hq, __half* __restrict__ hk, __half* __restrict__ hvt,
    const float* __restrict__ xres, float* __restrict__ of)
{
    extern __shared__ uint32_t gsm[];
    const uint32_t sbase = smem_u32(gsm);

    const int tid = threadIdx.x;
    const int wid = tid >> 5, lane = tid & 31;
    const int g = lane >> 2, t = lane & 3;
    const int wm = wid >> 1, wn = wid & 1;
    const int m0 = blockIdx.y * 256;
    const int n0 = blockIdx.x * 128;

    const int lrow  = (lane & 7) + ((lane >> 3) & 1) * 8;
    const int lcol4 = (lane >> 4) * 4;

    float acc[4][8][4];
#pragma unroll
    for (int i = 0; i < 4; i++)
#pragma unroll
        for (int j = 0; j < 8; j++)
#pragma unroll
            for (int r = 0; r < 4; r++) acc[i][j][r] = 0.f;

    // A: 256 rows x 32 halves = 1024 cp16 (4/thread); B: 128 rows = 512 cp16 (2/thread)
#define G_LOAD(abase, bbase, kt) do {                                             \
    _Pragma("unroll")                                                             \
    for (int i = 0; i < 4; i++) {                                                 \
        int j = tid + i * 256;                                                    \
        int r = j >> 2, cq = j & 3;                                               \
        cp16((abase) + (uint32_t)(r * GPAD + cq * 4) * 4,                         \
             A + (size_t)(m0 + r) * 1024 + (kt) * 32 + cq * 8);                   \
    }                                                                             \
    _Pragma("unroll")                                                             \
    for (int i = 0; i < 2; i++) {                                                 \
        int j = tid + i * 256;                                                    \
        int r = j >> 2, cq = j & 3;                                               \
        cp16((bbase) + (uint32_t)(r * GPAD + cq * 4) * 4,                         \
             W + (size_t)(n0 + r) * 1024 + (kt) * 32 + cq * 8);                   \
    }                                                                             \
    CP_COMMIT();                                                                  \
} while (0)

    G_LOAD(sbase, sbase + ASTAGE_B, 0);
    G_LOAD(sbase + STAGE_B, sbase + STAGE_B + ASTAGE_B, 1);

    int st = 0, stl = 2;
    for (int kt = 0; kt < 32; kt++) {
        if (kt < 31) { CP_WAIT1(); } else { CP_WAIT0(); }
        __syncthreads();
        if (kt + 2 < 32) {
            const uint32_t la = sbase + (uint32_t)stl * STAGE_B;
            G_LOAD(la, la + ASTAGE_B, kt + 2);
        }
        const uint32_t aoff = sbase + (uint32_t)st * STAGE_B;
        const uint32_t boff = aoff + ASTAGE_B;

#pragma unroll
        for (int ks = 0; ks < 2; ks++) {
            uint32_t af[4][4];
#pragma unroll
            for (int mt = 0; mt < 4; mt++)
                ldsm4(af[mt][0], af[mt][1], af[mt][2], af[mt][3],
                      aoff + 4u * ((wm * 64 + mt * 16 + lrow) * GPAD + ks * 8 + lcol4));
#pragma unroll
            for (int np = 0; np < 4; np++) {
                uint32_t r0, r1, r2, r3;
                ldsm4(r0, r1, r2, r3,
                      boff + 4u * ((wn * 64 + np * 16 + lrow) * GPAD + ks * 8 + lcol4));
#pragma unroll
                for (int mt = 0; mt < 4; mt++) {
                    mma16(acc[mt][2 * np],     af[mt], r0, r2);
                    mma16(acc[mt][2 * np + 1], af[mt], r1, r3);
                }
            }
        }
        if (++st == 3) st = 0;
        if (++stl == 3) stl = 0;
    }

    // epilogue
#pragma unroll
    for (int mt = 0; mt < 4; mt++) {
        const int r0 = m0 + wm * 64 + mt * 16 + g;
#pragma unroll
        for (int nt = 0; nt < 8; nt++) {
            const int col = n0 + wn * 64 + nt * 8 + 2 * t;
            if (QKV) {
                const int mat = col >> 10, nl = col & 1023;
                const float* bias = (mat == 0 ? b0 : mat == 1 ? b1 : b2);
                const int h = nl >> 6, d = nl & 63;
                const float2 bv = *(const float2*)(bias + nl);
                const int b = r0 >> 11, s = r0 & 2047;
                float v0 = acc[mt][nt][0] + bv.x, v1 = acc[mt][nt][1] + bv.y;
                float v2 = acc[mt][nt][2] + bv.x, v3 = acc[mt][nt][3] + bv.y;
                if (mat == 0) {
                    v0 *= QSCALE; v1 *= QSCALE; v2 *= QSCALE; v3 *= QSCALE;
                    __half* p = hq + ((size_t)((b * 16 + h) * 2048 + s)) * 64 + d;
                    *(__half2*)p = __floats2half2_rn(v0, v1);
                    *(__half2*)(p + 8 * 64) = __floats2half2_rn(v2, v3);
                } else if (mat == 1) {
                    __half* p = hk + ((size_t)((b * 16 + h) * 2048 + s)) * 64 + d;
                    *(__half2*)p = __floats2half2_rn(v0, v1);
                    *(__half2*)(p + 8 * 64) = __floats2half2_rn(v2, v3);
                } else {
                    __half* vp = hvt + (size_t)(b * 16 + h) * 64 * S_LEN;
                    vp[(size_t)d * S_LEN + s]           = __float2half_rn(v0);
                    vp[(size_t)(d + 1) * S_LEN + s]     = __float2half_rn(v1);
                    vp[(size_t)d * S_LEN + s + 8]       = __float2half_rn(v2);
                    vp[(size_t)(d + 1) * S_LEN + s + 8] = __float2half_rn(v3);
                }
            } else {
                const float2 bv = *(const float2*)(b0 + col);
                const float2 x0 = *(const float2*)(xres + (size_t)r0 * 1024 + col);
                const float2 x1 = *(const float2*)(xres + (size_t)(r0 + 8) * 1024 + col);
                float* p = of + (size_t)r0 * 1024 + col;
                *(float2*)p = make_float2(acc[mt][nt][0] + bv.x + x0.x,
                                          acc[mt][nt][1] + bv.y + x0.y);
                *(float2*)(p + 8 * 1024) = make_float2(acc[mt][nt][2] + bv.x + x1.x,
                                                       acc[mt][nt][3] + bv.y + x1.y);
            }
        }
    }
}

// ======================= fp16 flash attention ==============================
// CTA: 128 queries, 8 warps. KV tiles of 128 keys (two 64-key halves).
// P in registers, l via ones-MMA, POFF folded into accumulator init.
#define APK  36
#define APV  68
#define QU   (128 * APK)
#define KU   (128 * APK)
#define VU   (64 * APV)
#define ATTN_SMEM ((QU + 2 * KU + 2 * VU) * 4)   // 90112 bytes

__global__ __launch_bounds__(256, 2) void attn_h(
    const __half* __restrict__ Q, const __half* __restrict__ K,
    const __half* __restrict__ Vt, __half* __restrict__ Ctx)
{
    extern __shared__ uint32_t smu[];
    const uint32_t uQ = smem_u32(smu);
    const uint32_t uK[2] = {uQ + 4u * QU, uQ + 4u * (QU + KU)};
    const uint32_t uV[2] = {uQ + 4u * (QU + 2 * KU), uQ + 4u * (QU + 2 * KU + VU)};

    const int bh = blockIdx.y;
    const int q0 = blockIdx.x * 128;
    const int tid = threadIdx.x;
    const int wid = tid >> 5, lane = tid & 31;
    const int g = lane >> 2, t = lane & 3;
    const int lrow  = (lane & 7) + ((lane >> 3) & 1) * 8;
    const int lcol4 = (lane >> 4) * 4;

    const __half* Qb = Q  + (size_t)bh * S_LEN * 64;
    const __half* Kb = K  + (size_t)bh * S_LEN * 64;
    const __half* Vb = Vt + (size_t)bh * 64 * S_LEN;

#define LOAD_K(st, kt) do { _Pragma("unroll") for (int i = 0; i < 4; i++) { \
    int j = tid + i * 256; int r = j >> 3, cq = j & 7;                      \
    cp16(uK[st] + (uint32_t)(r * APK + cq * 4) * 4,                         \
         Kb + (size_t)((kt) * 128 + r) * 64 + cq * 8); } } while (0)
#define LOAD_V(st, kt) do { _Pragma("unroll") for (int i = 0; i < 4; i++) { \
    int j = tid + i * 256; int r = j >> 4, cq = j & 15;                     \
    cp16(uV[st] + (uint32_t)(r * APV + cq * 4) * 4,                         \
         Vb + (size_t)r * S_LEN + (kt) * 128 + cq * 8); } } while (0)

    // prologue: Q + K0 + V0
#pragma unroll
    for (int i = 0; i < 4; i++) {
        int j = tid + i * 256; int r = j >> 3, cq = j & 7;
        cp16(uQ + (uint32_t)(r * APK + cq * 4) * 4, Qb + (size_t)(q0 + r) * 64 + cq * 8);
    }
    LOAD_K(0, 0); LOAD_V(0, 0); CP_COMMIT();
    CP_WAIT0();
    __syncthreads();

    const int rbase = wid * 16 + g;

    uint32_t qf[4][4];
#pragma unroll
    for (int ks = 0; ks < 4; ks++)
        ldsm4(qf[ks][0], qf[ks][1], qf[ks][2], qf[ks][3],
              uQ + 4u * ((wid * 16 + lrow) * APK + ks * 8 + lcol4));

    float lacc[4] = {0.f, 0.f, 0.f, 0.f};
    float oacc[8][4];
#pragma unroll
    for (int i = 0; i < 8; i++)
#pragma unroll
        for (int r = 0; r < 4; r++) oacc[i][r] = 0.f;

    for (int kt = 0; kt < 16; kt++) {
        const int st = kt & 1;
        if (kt > 0) { CP_WAIT0(); __syncthreads(); }
        if (kt < 15) { LOAD_K(st ^ 1, kt + 1); LOAD_V(st ^ 1, kt + 1); CP_COMMIT(); }

#pragma unroll
        for (int hf = 0; hf < 2; hf++) {
            float sacc[8][4];
#pragma unroll
            for (int i = 0; i < 8; i++)
#pragma unroll
                for (int r = 0; r < 4; r++) sacc[i][r] = -POFF;

#pragma unroll
            for (int ks = 0; ks < 4; ks++) {
#pragma unroll
                for (int np = 0; np < 4; np++) {
                    uint32_t r0, r1, r2, r3;
                    ldsm4(r0, r1, r2, r3,
                          uK[st] + 4u * ((hf * 64 + np * 16 + lrow) * APK + ks * 8 + lcol4));
                    mma16(sacc[2 * np],     qf[ks], r0, r2);
                    mma16(sacc[2 * np + 1], qf[ks], r1, r3);
                }
            }

#pragma unroll
            for (int ks = 0; ks < 4; ks++) {
                uint32_t pf[4];
                pf[0] = pexp2(sacc[2 * ks][0],     sacc[2 * ks][1]);
                pf[1] = pexp2(sacc[2 * ks][2],     sacc[2 * ks][3]);
                pf[2] = pexp2(sacc[2 * ks + 1][0], sacc[2 * ks + 1][1]);
                pf[3] = pexp2(sacc[2 * ks + 1][2], sacc[2 * ks + 1][3]);

                mma16(lacc, pf, ONES2, ONES2);

#pragma unroll
                for (int np = 0; np < 4; np++) {
                    uint32_t r0, r1, r2, r3;
                    ldsm4(r0, r1, r2, r3,
                          uV[st] + 4u * ((np * 16 + lrow) * APV + hf * 32 + ks * 8 + lcol4));
                    mma16(oacc[2 * np],     pf, r0, r2);
                    mma16(oacc[2 * np + 1], pf, r1, r3);
                }
            }
        }
    }

    const float inv0 = 1.f / lacc[0], inv1 = 1.f / lacc[2];
    const int b = bh >> 4, h = bh & 15;
    const int row0 = q0 + rbase;
    __half* base0 = Ctx + ((size_t)(b * 2048 + row0)) * 1024 + h * 64;
#pragma unroll
    for (int nt = 0; nt < 8; nt++) {
        const int col = nt * 8 + 2 * t;
        *(__half2*)(base0 + col) = __floats2half2_rn(oacc[nt][0] * inv0, oacc[nt][1] * inv0);
        *(__half2*)(base0 + 8 * 1024 + col) = __floats2half2_rn(oacc[nt][2] * inv1,
                                                                oacc[nt][3] * inv1);
    }
}

// ======================= fused prep: weights transpose + x convert ========
__global__ __launch_bounds__(256) void prep_all(
    const float* __restrict__ Wq, const float* __restrict__ Wk,
    const float* __restrict__ Wv, const float* __restrict__ Wo,
    const float* __restrict__ x,
    __half* __restrict__ Wh, __half* __restrict__ Woh, __half* __restrict__ xh)
{
    const int z = blockIdx.z;
    const int tx = threadIdx.x, ty = threadIdx.y;   // 32 x 8
    if (z == 4) {
        const int tl = (blockIdx.y * 32 + blockIdx.x) * 256 + ty * 32 + tx;
#pragma unroll
        for (int k = 0; k < 4; k++) {
            const int i = tl + k * 262144;
            float4 v = ((const float4*)x)[i];
            ((__half2*)xh)[2 * i]     = __floats2half2_rn(v.x, v.y);
            ((__half2*)xh)[2 * i + 1] = __floats2half2_rn(v.z, v.w);
        }
        return;
    }
    __shared__ float tb[32][33];
    const float* src = (z == 0) ? Wq : (z == 1) ? Wk : (z == 2) ? Wv : Wo;
    __half* dst = (z < 3) ? (Wh + (size_t)z * D_MOD * D_MOD) : Woh;
    const int k0 = blockIdx.x * 32, n0 = blockIdx.y * 32;
#pragma unroll
    for (int i = 0; i < 4; i++)
        tb[ty + i * 8][tx] = src[(size_t)(k0 + ty + i * 8) * D_MOD + n0 + tx];
    __syncthreads();
#pragma unroll
    for (int i = 0; i < 4; i++)
        dst[(size_t)(n0 + ty + i * 8) * D_MOD + k0 + tx] = __float2half_rn(tb[tx][ty + i * 8]);
}

// ---------------- LayerNorm (input h already includes residual) -----------
__global__ __launch_bounds__(256) void ln_kernel(
    const float* __restrict__ hin,
    const float* __restrict__ gamma, const float* __restrict__ beta,
    float* __restrict__ out)
{
    const int row = blockIdx.x;
    const int tid = threadIdx.x;

    const float4 h = ((const float4*)(hin + (size_t)row * D_MOD))[tid];

    float sum = h.x + h.y + h.z + h.w;
    float ssq = h.x * h.x + h.y * h.y + h.z * h.z + h.w * h.w;
#pragma unroll
    for (int o = 16; o > 0; o >>= 1) {
        sum += __shfl_xor_sync(0xffffffffu, sum, o);
        ssq += __shfl_xor_sync(0xffffffffu, ssq, o);
    }
    __shared__ float rs[8], rq[8];
    const int warp = tid >> 5, lane = tid & 31;
    if (lane == 0) { rs[warp] = sum; rq[warp] = ssq; }
    __syncthreads();
    float ts = 0.f, tq = 0.f;
#pragma unroll
    for (int i = 0; i < 8; i++) { ts += rs[i]; tq += rq[i]; }

    const float mu   = ts * (1.f / (float)D_MOD);
    const float var  = tq * (1.f / (float)D_MOD) - mu * mu;
    const float rstd = rsqrtf(var + 1e-5f);

    const float4 gg = ((const float4*)gamma)[tid];
    const float4 bb = ((const float4*)beta)[tid];
    float4 o;
    o.x = (h.x - mu) * rstd * gg.x + bb.x;
    o.y = (h.y - mu) * rstd * gg.y + bb.y;
    o.z = (h.z - mu) * rstd * gg.z + bb.z;
    o.w = (h.w - mu) * rstd * gg.w + bb.w;
    ((float4*)(out + (size_t)row * D_MOD))[tid] = o;
}

// ---------------- launch ----------------------------------------------------
extern "C" void kernel_launch(void* const* d_in, const int* in_sizes, int n_in,
                              void* d_out, int out_size)
{
    const float* x  = (const float*)d_in[0];
    const float* Wq = (const float*)d_in[1];
    const float* bq = (const float*)d_in[2];
    const float* Wk = (const float*)d_in[3];
    const float* bk = (const float*)d_in[4];
    const float* Wv = (const float*)d_in[5];
    const float* bv = (const float*)d_in[6];
    const float* Wo = (const float*)d_in[7];
    const float* bo = (const float*)d_in[8];
    const float* ga = (const float*)d_in[9];
    const float* be = (const float*)d_in[10];
    float* out = (float*)d_out;

    __half *Xh, *Wh, *Woh, *Qp, *Kp, *Vtp, *Ch;
    float *Pp;
    cudaGetSymbolAddress((void**)&Xh,  g_xh);
    cudaGetSymbolAddress((void**)&Wh,  g_Wh);
    cudaGetSymbolAddress((void**)&Woh, g_Woh);
    cudaGetSymbolAddress((void**)&Qp,  g_Q);
    cudaGetSymbolAddress((void**)&Kp,  g_K);
    cudaGetSymbolAddress((void**)&Vtp, g_Vt);
    cudaGetSymbolAddress((void**)&Ch,  g_ctxh);
    cudaGetSymbolAddress((void**)&Pp,  g_prj);

    cudaFuncSetAttribute(attn_h, cudaFuncAttributeMaxDynamicSharedMemorySize, ATTN_SMEM);
    cudaFuncSetAttribute(gemm_h<1>, cudaFuncAttributeMaxDynamicSharedMemorySize, GEMM_SMEM);
    cudaFuncSetAttribute(gemm_h<0>, cudaFuncAttributeMaxDynamicSharedMemorySize, GEMM_SMEM);

    prep_all<<<dim3(32, 32, 5), dim3(32, 8)>>>(Wq, Wk, Wv, Wo, x, Wh, Woh, Xh);

    // BM=256, BN=128: QKV grid (3072/128, 4096/256) = (24, 16)
    gemm_h<1><<<dim3(24, 16), 256, GEMM_SMEM>>>(Xh, Wh, bq, bk, bv, Qp, Kp, Vtp,
                                                nullptr, nullptr);

    attn_h<<<dim3(S_LEN / 128, NBH), 256, ATTN_SMEM>>>(Qp, Kp, Vtp, Ch);

    // out-proj grid (1024/128, 4096/256) = (8, 16)
    gemm_h<0><<<dim3(8, 16), 256, GEMM_SMEM>>>(Ch, Woh, bo, bo, bo,
                                               nullptr, nullptr, nullptr, x, Pp);

    ln_kernel<<<ROWS, 256>>>(Pp, ga, be, out);
}

// round 15
// speedup vs baseline: 1.0812x; 1.0812x over previous
#include <cuda_runtime.h>
#include <cuda_fp16.h>
#include <cstdint>
#include <math.h>

#define S_LEN 2048
#define D_MOD 1024
#define ROWS  4096          // B*S
#define NBH   32            // B*H
#define QSCALE 0.18033688011112042f   // 0.125 * log2(e)
#define POFF   8.0f                   // fixed exp2-domain offset (cancels in O/l)
#define ONES2  0x3C003C00u            // half2(1,1)

// ---------------- scratch (static; no allocations) ----------
__device__ __align__(128) __half g_xh [ROWS * D_MOD];
__device__ __align__(128) __half g_Wh [3 * D_MOD * D_MOD];    // [3072][1024] K-major fp16
__device__ __align__(128) __half g_Woh[D_MOD * D_MOD];
__device__ __align__(128) __half g_Q  [NBH * S_LEN * 64];     // pre-scaled by QSCALE
__device__ __align__(128) __half g_K  [NBH * S_LEN * 64];
__device__ __align__(128) __half g_Vt [NBH * 64 * S_LEN];     // [bh][dk][s] (written by GEMM)
__device__ __align__(128) __half g_ctxh[ROWS * D_MOD];
__device__ __align__(128) float  g_prj[ROWS * D_MOD];         // x + ctx@Wo + bo

// ---------------- helpers ----------------
__device__ __forceinline__ uint32_t smem_u32(const void* p) {
    uint32_t a;
    asm("{ .reg .u64 t; cvta.to.shared.u64 t, %1; cvt.u32.u64 %0, t; }" : "=r"(a) : "l"(p));
    return a;
}
__device__ __forceinline__ void cp16(uint32_t dst, const void* src) {
    asm volatile("cp.async.cg.shared.global [%0], [%1], 16;" :: "r"(dst), "l"(src) : "memory");
}
#define CP_COMMIT() asm volatile("cp.async.commit_group;" ::: "memory")
#define CP_WAIT0()  asm volatile("cp.async.wait_group 0;" ::: "memory")
#define CP_WAIT1()  asm volatile("cp.async.wait_group 1;" ::: "memory")

// p = exp2(half2(a, b)) — POFF already folded into the MMA accumulator init
__device__ __forceinline__ uint32_t pexp2(float a, float b) {
    __half2 h = __floats2half2_rn(a, b);
    uint32_t u = *reinterpret_cast<uint32_t*>(&h);
    uint32_t r;
    asm("ex2.approx.f16x2 %0, %1;" : "=r"(r) : "r"(u));
    return r;
}
__device__ __forceinline__ void mma16(float* d, const uint32_t* a, uint32_t b0, uint32_t b1) {
    asm volatile("mma.sync.aligned.m16n8k16.row.col.f32.f16.f16.f32 "
        "{%0,%1,%2,%3}, {%4,%5,%6,%7}, {%8,%9}, {%0,%1,%2,%3};"
        : "+f"(d[0]), "+f"(d[1]), "+f"(d[2]), "+f"(d[3])
        : "r"(a[0]), "r"(a[1]), "r"(a[2]), "r"(a[3]), "r"(b0), "r"(b1));
}
__device__ __forceinline__ void ldsm4(uint32_t& r0, uint32_t& r1, uint32_t& r2, uint32_t& r3,
                                      uint32_t addr) {
    asm volatile("ldmatrix.sync.aligned.m8n8.x4.shared.b16 {%0,%1,%2,%3}, [%4];"
        : "=r"(r0), "=r"(r1), "=r"(r2), "=r"(r3) : "r"(addr));
}

// ======================= fp16 mma.sync GEMM ================================
// BM=128, BN=128, BK=64 halves. 128 threads: 4 warps (2M x 2N), 64x64/warp.
// MMA/LDSM ratio 4.0; 2-stage cp.async pipeline; 2 CTAs/SM.
// QKV=1: Q/K written [B,H,S,64] (Q pre-scaled); V written TRANSPOSED.
// QKV=0: writes float prj = acc + bias + x (residual fused).
#define GPAD2 36                               // 32 data u32 + 4 pad
#define GSTAGE_B  (128 * GPAD2 * 4)            // 18432 B per matrix per stage
#define GEMM_SMEM (2 * 2 * GSTAGE_B)           // 73728 B

template <int QKV>
__global__ __launch_bounds__(128, 2) void gemm_h(
    const __half* __restrict__ A, const __half* __restrict__ W,
    const float* __restrict__ b0, const float* __restrict__ b1, const float* __restrict__ b2,
    __half* __restrict__ hq, __half* __restrict__ hk, __half* __restrict__ hvt,
    const float* __restrict__ xres, float* __restrict__ of)
{
    extern __shared__ uint32_t gsm[];
    const uint32_t sbase = smem_u32(gsm);

    const int tid = threadIdx.x;
    const int wid = tid >> 5, lane = tid & 31;
    const int g = lane >> 2, t = lane & 3;
    const int wm = wid >> 1, wn = wid & 1;       // 2M x 2N warps, 64x64 each
    const int m0 = blockIdx.y * 128;
    const int n0 = blockIdx.x * 128;

    const int lrow  = (lane & 7) + ((lane >> 3) & 1) * 8;
    const int lcol4 = (lane >> 4) * 4;

    float acc[4][8][4];
#pragma unroll
    for (int i = 0; i < 4; i++)
#pragma unroll
        for (int j = 0; j < 8; j++)
#pragma unroll
            for (int r = 0; r < 4; r++) acc[i][j][r] = 0.f;

    // per matrix: 128 rows x 64 halves = 1024 cp16; 128 threads -> 8/thread
#define G_LOAD(abase, bbase, kt) do {                                             \
    _Pragma("unroll")                                                             \
    for (int i = 0; i < 8; i++) {                                                 \
        int j = tid + i * 128;                                                    \
        int r = j >> 3, cq = j & 7;                                               \
        cp16((abase) + (uint32_t)(r * GPAD2 + cq * 4) * 4,                        \
             A + (size_t)(m0 + r) * 1024 + (kt) * 64 + cq * 8);                   \
        cp16((bbase) + (uint32_t)(r * GPAD2 + cq * 4) * 4,                        \
             W + (size_t)(n0 + r) * 1024 + (kt) * 64 + cq * 8);                   \
    }                                                                             \
    CP_COMMIT();                                                                  \
} while (0)

    G_LOAD(sbase, sbase + GSTAGE_B, 0);

    for (int kt = 0; kt < 16; kt++) {
        const int st = kt & 1;
        if (kt < 15) {
            const uint32_t la = sbase + (uint32_t)(st ^ 1) * (2 * GSTAGE_B);
            G_LOAD(la, la + GSTAGE_B, kt + 1);
            CP_WAIT1();
        } else {
            CP_WAIT0();
        }
        __syncthreads();
        const uint32_t aoff = sbase + (uint32_t)st * (2 * GSTAGE_B);
        const uint32_t boff = aoff + GSTAGE_B;

#pragma unroll
        for (int ks = 0; ks < 4; ks++) {
            uint32_t af[4][4];
#pragma unroll
            for (int mt = 0; mt < 4; mt++)
                ldsm4(af[mt][0], af[mt][1], af[mt][2], af[mt][3],
                      aoff + 4u * ((wm * 64 + mt * 16 + lrow) * GPAD2 + ks * 8 + lcol4));
#pragma unroll
            for (int np = 0; np < 4; np++) {
                uint32_t r0, r1, r2, r3;
                ldsm4(r0, r1, r2, r3,
                      boff + 4u * ((wn * 64 + np * 16 + lrow) * GPAD2 + ks * 8 + lcol4));
#pragma unroll
                for (int mt = 0; mt < 4; mt++) {
                    mma16(acc[mt][2 * np],     af[mt], r0, r2);
                    mma16(acc[mt][2 * np + 1], af[mt], r1, r3);
                }
            }
        }
        __syncthreads();
    }

    // epilogue
#pragma unroll
    for (int mt = 0; mt < 4; mt++) {
        const int r0 = m0 + wm * 64 + mt * 16 + g;
#pragma unroll
        for (int nt = 0; nt < 8; nt++) {
            const int col = n0 + wn * 64 + nt * 8 + 2 * t;
            if (QKV) {
                const int mat = col >> 10, nl = col & 1023;
                const float* bias = (mat == 0 ? b0 : mat == 1 ? b1 : b2);
                const int h = nl >> 6, d = nl & 63;
                const float2 bv = *(const float2*)(bias + nl);
                const int b = r0 >> 11, s = r0 & 2047;
                float v0 = acc[mt][nt][0] + bv.x, v1 = acc[mt][nt][1] + bv.y;
                float v2 = acc[mt][nt][2] + bv.x, v3 = acc[mt][nt][3] + bv.y;
                if (mat == 0) {
                    v0 *= QSCALE; v1 *= QSCALE; v2 *= QSCALE; v3 *= QSCALE;
                    __half* p = hq + ((size_t)((b * 16 + h) * 2048 + s)) * 64 + d;
                    *(__half2*)p = __floats2half2_rn(v0, v1);
                    *(__half2*)(p + 8 * 64) = __floats2half2_rn(v2, v3);
                } else if (mat == 1) {
                    __half* p = hk + ((size_t)((b * 16 + h) * 2048 + s)) * 64 + d;
                    *(__half2*)p = __floats2half2_rn(v0, v1);
                    *(__half2*)(p + 8 * 64) = __floats2half2_rn(v2, v3);
                } else {
                    __half* vp = hvt + (size_t)(b * 16 + h) * 64 * S_LEN;
                    vp[(size_t)d * S_LEN + s]           = __float2half_rn(v0);
                    vp[(size_t)(d + 1) * S_LEN + s]     = __float2half_rn(v1);
                    vp[(size_t)d * S_LEN + s + 8]       = __float2half_rn(v2);
                    vp[(size_t)(d + 1) * S_LEN + s + 8] = __float2half_rn(v3);
                }
            } else {
                const float2 bv = *(const float2*)(b0 + col);
                const float2 x0 = *(const float2*)(xres + (size_t)r0 * 1024 + col);
                const float2 x1 = *(const float2*)(xres + (size_t)(r0 + 8) * 1024 + col);
                float* p = of + (size_t)r0 * 1024 + col;
                *(float2*)p = make_float2(acc[mt][nt][0] + bv.x + x0.x,
                                          acc[mt][nt][1] + bv.y + x0.y);
                *(float2*)(p + 8 * 1024) = make_float2(acc[mt][nt][2] + bv.x + x1.x,
                                                       acc[mt][nt][3] + bv.y + x1.y);
            }
        }
    }
}

// ======================= fp16 flash attention ==============================
// CTA: 128 queries, 8 warps. KV tiles of 128 keys (two 64-key halves).
// P in registers, l via ones-MMA, POFF folded into accumulator init.
#define APK  36
#define APV  68
#define QU   (128 * APK)
#define KU   (128 * APK)
#define VU   (64 * APV)
#define ATTN_SMEM ((QU + 2 * KU + 2 * VU) * 4)   // 90112 bytes

__global__ __launch_bounds__(256, 2) void attn_h(
    const __half* __restrict__ Q, const __half* __restrict__ K,
    const __half* __restrict__ Vt, __half* __restrict__ Ctx)
{
    extern __shared__ uint32_t smu[];
    const uint32_t uQ = smem_u32(smu);
    const uint32_t uK[2] = {uQ + 4u * QU, uQ + 4u * (QU + KU)};
    const uint32_t uV[2] = {uQ + 4u * (QU + 2 * KU), uQ + 4u * (QU + 2 * KU + VU)};

    const int bh = blockIdx.y;
    const int q0 = blockIdx.x * 128;
    const int tid = threadIdx.x;
    const int wid = tid >> 5, lane = tid & 31;
    const int g = lane >> 2, t = lane & 3;
    const int lrow  = (lane & 7) + ((lane >> 3) & 1) * 8;
    const int lcol4 = (lane >> 4) * 4;

    const __half* Qb = Q  + (size_t)bh * S_LEN * 64;
    const __half* Kb = K  + (size_t)bh * S_LEN * 64;
    const __half* Vb = Vt + (size_t)bh * 64 * S_LEN;

#define LOAD_K(st, kt) do { _Pragma("unroll") for (int i = 0; i < 4; i++) { \
    int j = tid + i * 256; int r = j >> 3, cq = j & 7;                      \
    cp16(uK[st] + (uint32_t)(r * APK + cq * 4) * 4,                         \
         Kb + (size_t)((kt) * 128 + r) * 64 + cq * 8); } } while (0)
#define LOAD_V(st, kt) do { _Pragma("unroll") for (int i = 0; i < 4; i++) { \
    int j = tid + i * 256; int r = j >> 4, cq = j & 15;                     \
    cp16(uV[st] + (uint32_t)(r * APV + cq * 4) * 4,                         \
         Vb + (size_t)r * S_LEN + (kt) * 128 + cq * 8); } } while (0)

    // prologue: Q + K0 + V0
#pragma unroll
    for (int i = 0; i < 4; i++) {
        int j = tid + i * 256; int r = j >> 3, cq = j & 7;
        cp16(uQ + (uint32_t)(r * APK + cq * 4) * 4, Qb + (size_t)(q0 + r) * 64 + cq * 8);
    }
    LOAD_K(0, 0); LOAD_V(0, 0); CP_COMMIT();
    CP_WAIT0();
    __syncthreads();

    const int rbase = wid * 16 + g;

    uint32_t qf[4][4];
#pragma unroll
    for (int ks = 0; ks < 4; ks++)
        ldsm4(qf[ks][0], qf[ks][1], qf[ks][2], qf[ks][3],
              uQ + 4u * ((wid * 16 + lrow) * APK + ks * 8 + lcol4));

    float lacc[4] = {0.f, 0.f, 0.f, 0.f};
    float oacc[8][4];
#pragma unroll
    for (int i = 0; i < 8; i++)
#pragma unroll
        for (int r = 0; r < 4; r++) oacc[i][r] = 0.f;

    for (int kt = 0; kt < 16; kt++) {
        const int st = kt & 1;
        if (kt > 0) { CP_WAIT0(); __syncthreads(); }
        if (kt < 15) { LOAD_K(st ^ 1, kt + 1); LOAD_V(st ^ 1, kt + 1); CP_COMMIT(); }

#pragma unroll
        for (int hf = 0; hf < 2; hf++) {
            float sacc[8][4];
#pragma unroll
            for (int i = 0; i < 8; i++)
#pragma unroll
                for (int r = 0; r < 4; r++) sacc[i][r] = -POFF;

#pragma unroll
            for (int ks = 0; ks < 4; ks++) {
#pragma unroll
                for (int np = 0; np < 4; np++) {
                    uint32_t r0, r1, r2, r3;
                    ldsm4(r0, r1, r2, r3,
                          uK[st] + 4u * ((hf * 64 + np * 16 + lrow) * APK + ks * 8 + lcol4));
                    mma16(sacc[2 * np],     qf[ks], r0, r2);
                    mma16(sacc[2 * np + 1], qf[ks], r1, r3);
                }
            }

#pragma unroll
            for (int ks = 0; ks < 4; ks++) {
                uint32_t pf[4];
                pf[0] = pexp2(sacc[2 * ks][0],     sacc[2 * ks][1]);
                pf[1] = pexp2(sacc[2 * ks][2],     sacc[2 * ks][3]);
                pf[2] = pexp2(sacc[2 * ks + 1][0], sacc[2 * ks + 1][1]);
                pf[3] = pexp2(sacc[2 * ks + 1][2], sacc[2 * ks + 1][3]);

                mma16(lacc, pf, ONES2, ONES2);

#pragma unroll
                for (int np = 0; np < 4; np++) {
                    uint32_t r0, r1, r2, r3;
                    ldsm4(r0, r1, r2, r3,
                          uV[st] + 4u * ((np * 16 + lrow) * APV + hf * 32 + ks * 8 + lcol4));
                    mma16(oacc[2 * np],     pf, r0, r2);
                    mma16(oacc[2 * np + 1], pf, r1, r3);
                }
            }
        }
    }

    const float inv0 = 1.f / lacc[0], inv1 = 1.f / lacc[2];
    const int b = bh >> 4, h = bh & 15;
    const int row0 = q0 + rbase;
    __half* base0 = Ctx + ((size_t)(b * 2048 + row0)) * 1024 + h * 64;
#pragma unroll
    for (int nt = 0; nt < 8; nt++) {
        const int col = nt * 8 + 2 * t;
        *(__half2*)(base0 + col) = __floats2half2_rn(oacc[nt][0] * inv0, oacc[nt][1] * inv0);
        *(__half2*)(base0 + 8 * 1024 + col) = __floats2half2_rn(oacc[nt][2] * inv1,
                                                                oacc[nt][3] * inv1);
    }
}

// ======================= fused prep: weights transpose + x convert ========
__global__ __launch_bounds__(256) void prep_all(
    const float* __restrict__ Wq, const float* __restrict__ Wk,
    const float* __restrict__ Wv, const float* __restrict__ Wo,
    const float* __restrict__ x,
    __half* __restrict__ Wh, __half* __restrict__ Woh, __half* __restrict__ xh)
{
    const int z = blockIdx.z;
    const int tx = threadIdx.x, ty = threadIdx.y;   // 32 x 8
    if (z == 4) {
        const int tl = (blockIdx.y * 32 + blockIdx.x) * 256 + ty * 32 + tx;
#pragma unroll
        for (int k = 0; k < 4; k++) {
            const int i = tl + k * 262144;
            float4 v = ((const float4*)x)[i];
            ((__half2*)xh)[2 * i]     = __floats2half2_rn(v.x, v.y);
            ((__half2*)xh)[2 * i + 1] = __floats2half2_rn(v.z, v.w);
        }
        return;
    }
    __shared__ float tb[32][33];
    const float* src = (z == 0) ? Wq : (z == 1) ? Wk : (z == 2) ? Wv : Wo;
    __half* dst = (z < 3) ? (Wh + (size_t)z * D_MOD * D_MOD) : Woh;
    const int k0 = blockIdx.x * 32, n0 = blockIdx.y * 32;
#pragma unroll
    for (int i = 0; i < 4; i++)
        tb[ty + i * 8][tx] = src[(size_t)(k0 + ty + i * 8) * D_MOD + n0 + tx];
    __syncthreads();
#pragma unroll
    for (int i = 0; i < 4; i++)
        dst[(size_t)(n0 + ty + i * 8) * D_MOD + k0 + tx] = __float2half_rn(tb[tx][ty + i * 8]);
}

// ---------------- LayerNorm (input h already includes residual) -----------
__global__ __launch_bounds__(256) void ln_kernel(
    const float* __restrict__ hin,
    const float* __restrict__ gamma, const float* __restrict__ beta,
    float* __restrict__ out)
{
    const int row = blockIdx.x;
    const int tid = threadIdx.x;

    const float4 h = ((const float4*)(hin + (size_t)row * D_MOD))[tid];

    float sum = h.x + h.y + h.z + h.w;
    float ssq = h.x * h.x + h.y * h.y + h.z * h.z + h.w * h.w;
#pragma unroll
    for (int o = 16; o > 0; o >>= 1) {
        sum += __shfl_xor_sync(0xffffffffu, sum, o);
        ssq += __shfl_xor_sync(0xffffffffu, ssq, o);
    }
    __shared__ float rs[8], rq[8];
    const int warp = tid >> 5, lane = tid & 31;
    if (lane == 0) { rs[warp] = sum; rq[warp] = ssq; }
    __syncthreads();
    float ts = 0.f, tq = 0.f;
#pragma unroll
    for (int i = 0; i < 8; i++) { ts += rs[i]; tq += rq[i]; }

    const float mu   = ts * (1.f / (float)D_MOD);
    const float var  = tq * (1.f / (float)D_MOD) - mu * mu;
    const float rstd = rsqrtf(var + 1e-5f);

    const float4 gg = ((const float4*)gamma)[tid];
    const float4 bb = ((const float4*)beta)[tid];
    float4 o;
    o.x = (h.x - mu) * rstd * gg.x + bb.x;
    o.y = (h.y - mu) * rstd * gg.y + bb.y;
    o.z = (h.z - mu) * rstd * gg.z + bb.z;
    o.w = (h.w - mu) * rstd * gg.w + bb.w;
    ((float4*)(out + (size_t)row * D_MOD))[tid] = o;
}

// ---------------- launch ----------------------------------------------------
extern "C" void kernel_launch(void* const* d_in, const int* in_sizes, int n_in,
                              void* d_out, int out_size)
{
    const float* x  = (const float*)d_in[0];
    const float* Wq = (const float*)d_in[1];
    const float* bq = (const float*)d_in[2];
    const float* Wk = (const float*)d_in[3];
    const float* bk = (const float*)d_in[4];
    const float* Wv = (const float*)d_in[5];
    const float* bv = (const float*)d_in[6];
    const float* Wo = (const float*)d_in[7];
    const float* bo = (const float*)d_in[8];
    const float* ga = (const float*)d_in[9];
    const float* be = (const float*)d_in[10];
    float* out = (float*)d_out;

    __half *Xh, *Wh, *Woh, *Qp, *Kp, *Vtp, *Ch;
    float *Pp;
    cudaGetSymbolAddress((void**)&Xh,  g_xh);
    cudaGetSymbolAddress((void**)&Wh,  g_Wh);
    cudaGetSymbolAddress((void**)&Woh, g_Woh);
    cudaGetSymbolAddress((void**)&Qp,  g_Q);
    cudaGetSymbolAddress((void**)&Kp,  g_K);
    cudaGetSymbolAddress((void**)&Vtp, g_Vt);
    cudaGetSymbolAddress((void**)&Ch,  g_ctxh);
    cudaGetSymbolAddress((void**)&Pp,  g_prj);

    cudaFuncSetAttribute(attn_h, cudaFuncAttributeMaxDynamicSharedMemorySize, ATTN_SMEM);
    cudaFuncSetAttribute(gemm_h<1>, cudaFuncAttributeMaxDynamicSharedMemorySize, GEMM_SMEM);
    cudaFuncSetAttribute(gemm_h<0>, cudaFuncAttributeMaxDynamicSharedMemorySize, GEMM_SMEM);

    prep_all<<<dim3(32, 32, 5), dim3(32, 8)>>>(Wq, Wk, Wv, Wo, x, Wh, Woh, Xh);

    gemm_h<1><<<dim3(24, 32), 128, GEMM_SMEM>>>(Xh, Wh, bq, bk, bv, Qp, Kp, Vtp,
                                                nullptr, nullptr);

    attn_h<<<dim3(S_LEN / 128, NBH), 256, ATTN_SMEM>>>(Qp, Kp, Vtp, Ch);

    gemm_h<0><<<dim3(8, 32), 128, GEMM_SMEM>>>(Ch, Woh, bo, bo, bo,
                                               nullptr, nullptr, nullptr, x, Pp);

    ln_kernel<<<ROWS, 256>>>(Pp, ga, be, out);
}

// round 16
// speedup vs baseline: 1.0960x; 1.0137x over previous
#include <cuda_runtime.h>
#include <cuda_fp16.h>
#include <cstdint>
#include <math.h>

#define S_LEN 2048
#define D_MOD 1024
#define ROWS  4096          // B*S
#define NBH   32            // B*H
#define QSCALE 0.18033688011112042f   // 0.125 * log2(e)
#define POFF   8.0f                   // fixed exp2-domain offset (cancels in O/l)
#define ONES2  0x3C003C00u            // half2(1,1)

// ---------------- scratch (static; no allocations) ----------
__device__ __align__(128) __half g_xh [ROWS * D_MOD];
__device__ __align__(128) __half g_Wh [3 * D_MOD * D_MOD];    // [3072][1024] K-major fp16
__device__ __align__(128) __half g_Woh[D_MOD * D_MOD];
__device__ __align__(128) __half g_Q  [NBH * S_LEN * 64];     // pre-scaled by QSCALE
__device__ __align__(128) __half g_K  [NBH * S_LEN * 64];
__device__ __align__(128) __half g_Vt [NBH * 64 * S_LEN];     // [bh][dk][s] (written by GEMM)
__device__ __align__(128) __half g_ctxh[ROWS * D_MOD];
__device__ __align__(128) float  g_prj[ROWS * D_MOD];         // x + ctx@Wo + bo

// ---------------- helpers ----------------
__device__ __forceinline__ uint32_t smem_u32(const void* p) {
    uint32_t a;
    asm("{ .reg .u64 t; cvta.to.shared.u64 t, %1; cvt.u32.u64 %0, t; }" : "=r"(a) : "l"(p));
    return a;
}
__device__ __forceinline__ void cp16(uint32_t dst, const void* src) {
    asm volatile("cp.async.cg.shared.global [%0], [%1], 16;" :: "r"(dst), "l"(src) : "memory");
}
#define CP_COMMIT() asm volatile("cp.async.commit_group;" ::: "memory")
#define CP_WAIT0()  asm volatile("cp.async.wait_group 0;" ::: "memory")
#define CP_WAIT1()  asm volatile("cp.async.wait_group 1;" ::: "memory")

// p = exp2(half2(a, b)) — POFF already folded into the MMA accumulator init
__device__ __forceinline__ uint32_t pexp2(float a, float b) {
    __half2 h = __floats2half2_rn(a, b);
    uint32_t u = *reinterpret_cast<uint32_t*>(&h);
    uint32_t r;
    asm("ex2.approx.f16x2 %0, %1;" : "=r"(r) : "r"(u));
    return r;
}
__device__ __forceinline__ void mma16(float* d, const uint32_t* a, uint32_t b0, uint32_t b1) {
    asm volatile("mma.sync.aligned.m16n8k16.row.col.f32.f16.f16.f32 "
        "{%0,%1,%2,%3}, {%4,%5,%6,%7}, {%8,%9}, {%0,%1,%2,%3};"
        : "+f"(d[0]), "+f"(d[1]), "+f"(d[2]), "+f"(d[3])
        : "r"(a[0]), "r"(a[1]), "r"(a[2]), "r"(a[3]), "r"(b0), "r"(b1));
}
__device__ __forceinline__ void ldsm4(uint32_t& r0, uint32_t& r1, uint32_t& r2, uint32_t& r3,
                                      uint32_t addr) {
    asm volatile("ldmatrix.sync.aligned.m8n8.x4.shared.b16 {%0,%1,%2,%3}, [%4];"
        : "=r"(r0), "=r"(r1), "=r"(r2), "=r"(r3) : "r"(addr));
}

// ======================= fp16 mma.sync GEMM (BK=64, 3-stage) ===============
// C[4096, N] = A[4096,1024] @ W[N,1024]^T + bias.  BM=BN=128, BK=64 halves.
// 8 warps: wm = wid&1 (64 M-rows), wn = wid>>1 (32 N-cols). regs=128, 2 CTAs/SM.
// QKV=1: Q/K written [B,H,S,64] (Q pre-scaled); V written TRANSPOSED [bh][dk][s].
// QKV=0: writes float prj = acc + bias + x (residual fused).
#define GPAD2 36                               // 32 data u32 + 4 pad
#define GSTAGE_B  (128 * GPAD2 * 4)            // 18432 B per matrix per stage
#define GEMM_SMEM (3 * 2 * GSTAGE_B)           // 110592 B

template <int QKV>
__global__ __launch_bounds__(256, 2) void gemm_h(
    const __half* __restrict__ A, const __half* __restrict__ W,
    const float* __restrict__ b0, const float* __restrict__ b1, const float* __restrict__ b2,
    __half* __restrict__ hq, __half* __restrict__ hk, __half* __restrict__ hvt,
    const float* __restrict__ xres, float* __restrict__ of)
{
    extern __shared__ uint32_t gsm[];
    const uint32_t sbase = smem_u32(gsm);

    const int tid = threadIdx.x;
    const int wid = tid >> 5, lane = tid & 31;
    const int g = lane >> 2, t = lane & 3;
    const int wm = wid & 1, wn = wid >> 1;       // warp 64 (M) x 32 (N)
    const int m0 = blockIdx.y * 128;
    const int n0 = blockIdx.x * 128;

    const int lrow  = (lane & 7) + ((lane >> 3) & 1) * 8;
    const int lcol4 = (lane >> 4) * 4;

    float acc[4][4][4];
#pragma unroll
    for (int i = 0; i < 4; i++)
#pragma unroll
        for (int j = 0; j < 4; j++)
#pragma unroll
            for (int r = 0; r < 4; r++) acc[i][j][r] = 0.f;

    // 128 rows x 64 halves per matrix: 1024 cp16 -> 4 per thread
#define G_LOAD(abase, bbase, kt) do {                                             \
    _Pragma("unroll")                                                             \
    for (int i = 0; i < 4; i++) {                                                 \
        int j = tid + i * 256;                                                    \
        int r = j >> 3, cq = j & 7;                                               \
        cp16((abase) + (uint32_t)(r * GPAD2 + cq * 4) * 4,                        \
             A + (size_t)(m0 + r) * 1024 + (kt) * 64 + cq * 8);                   \
        cp16((bbase) + (uint32_t)(r * GPAD2 + cq * 4) * 4,                        \
             W + (size_t)(n0 + r) * 1024 + (kt) * 64 + cq * 8);                   \
    }                                                                             \
    CP_COMMIT();                                                                  \
} while (0)

    G_LOAD(sbase, sbase + GSTAGE_B, 0);
    G_LOAD(sbase + 2 * GSTAGE_B, sbase + 3 * GSTAGE_B, 1);

    int st = 0;       // stage of tile kt
    int stl = 2;      // stage for tile kt+2
    for (int kt = 0; kt < 16; kt++) {
        if (kt < 15) { CP_WAIT1(); } else { CP_WAIT0(); }
        __syncthreads();
        if (kt + 2 < 16) {
            const uint32_t la = sbase + (uint32_t)stl * (2 * GSTAGE_B);
            G_LOAD(la, la + GSTAGE_B, kt + 2);
        }
        const uint32_t aoff = sbase + (uint32_t)st * (2 * GSTAGE_B);
        const uint32_t boff = aoff + GSTAGE_B;

#pragma unroll
        for (int ks = 0; ks < 4; ks++) {
            uint32_t af[4][4];
#pragma unroll
            for (int mt = 0; mt < 4; mt++)
                ldsm4(af[mt][0], af[mt][1], af[mt][2], af[mt][3],
                      aoff + 4u * ((wm * 64 + mt * 16 + lrow) * GPAD2 + ks * 8 + lcol4));
#pragma unroll
            for (int np = 0; np < 2; np++) {
                uint32_t r0, r1, r2, r3;
                ldsm4(r0, r1, r2, r3,
                      boff + 4u * ((wn * 32 + np * 16 + lrow) * GPAD2 + ks * 8 + lcol4));
#pragma unroll
                for (int mt = 0; mt < 4; mt++) {
                    mma16(acc[mt][2 * np],     af[mt], r0, r2);
                    mma16(acc[mt][2 * np + 1], af[mt], r1, r3);
                }
            }
        }
        if (++st == 3) st = 0;
        if (++stl == 3) stl = 0;
    }

    // epilogue
#pragma unroll
    for (int mt = 0; mt < 4; mt++) {
        const int r0 = m0 + wm * 64 + mt * 16 + g;
#pragma unroll
        for (int nt = 0; nt < 4; nt++) {
            const int col = n0 + wn * 32 + nt * 8 + 2 * t;
            if (QKV) {
                const int mat = col >> 10, nl = col & 1023;
                const float* bias = (mat == 0 ? b0 : mat == 1 ? b1 : b2);
                const int h = nl >> 6, d = nl & 63;
                const float2 bv = *(const float2*)(bias + nl);
                const int b = r0 >> 11, s = r0 & 2047;
                float v0 = acc[mt][nt][0] + bv.x, v1 = acc[mt][nt][1] + bv.y;
                float v2 = acc[mt][nt][2] + bv.x, v3 = acc[mt][nt][3] + bv.y;
                if (mat == 0) {
                    v0 *= QSCALE; v1 *= QSCALE; v2 *= QSCALE; v3 *= QSCALE;
                    __half* p = hq + ((size_t)((b * 16 + h) * 2048 + s)) * 64 + d;
                    *(__half2*)p = __floats2half2_rn(v0, v1);
                    *(__half2*)(p + 8 * 64) = __floats2half2_rn(v2, v3);
                } else if (mat == 1) {
                    __half* p = hk + ((size_t)((b * 16 + h) * 2048 + s)) * 64 + d;
                    *(__half2*)p = __floats2half2_rn(v0, v1);
                    *(__half2*)(p + 8 * 64) = __floats2half2_rn(v2, v3);
                } else {
                    __half* vp = hvt + (size_t)(b * 16 + h) * 64 * S_LEN;
                    vp[(size_t)d * S_LEN + s]           = __float2half_rn(v0);
                    vp[(size_t)(d + 1) * S_LEN + s]     = __float2half_rn(v1);
                    vp[(size_t)d * S_LEN + s + 8]       = __float2half_rn(v2);
                    vp[(size_t)(d + 1) * S_LEN + s + 8] = __float2half_rn(v3);
                }
            } else {
                const float2 bv = *(const float2*)(b0 + col);
                const float2 x0 = *(const float2*)(xres + (size_t)r0 * 1024 + col);
                const float2 x1 = *(const float2*)(xres + (size_t)(r0 + 8) * 1024 + col);
                float* p = of + (size_t)r0 * 1024 + col;
                *(float2*)p = make_float2(acc[mt][nt][0] + bv.x + x0.x,
                                          acc[mt][nt][1] + bv.y + x0.y);
                *(float2*)(p + 8 * 1024) = make_float2(acc[mt][nt][2] + bv.x + x1.x,
                                                       acc[mt][nt][3] + bv.y + x1.y);
            }
        }
    }
}

// ======================= fp16 flash attention ==============================
// CTA: 128 queries, 8 warps. KV tiles of 128 keys (two 64-key halves).
// P in registers, row sums via dual ones-MMA accumulators (chain split),
// POFF folded into accumulator init.
#define APK  36
#define APV  68
#define QU   (128 * APK)
#define KU   (128 * APK)
#define VU   (64 * APV)
#define ATTN_SMEM ((QU + 2 * KU + 2 * VU) * 4)   // 90112 bytes

__global__ __launch_bounds__(256, 2) void attn_h(
    const __half* __restrict__ Q, const __half* __restrict__ K,
    const __half* __restrict__ Vt, __half* __restrict__ Ctx)
{
    extern __shared__ uint32_t smu[];
    const uint32_t uQ = smem_u32(smu);
    const uint32_t uK[2] = {uQ + 4u * QU, uQ + 4u * (QU + KU)};
    const uint32_t uV[2] = {uQ + 4u * (QU + 2 * KU), uQ + 4u * (QU + 2 * KU + VU)};

    const int bh = blockIdx.y;
    const int q0 = blockIdx.x * 128;
    const int tid = threadIdx.x;
    const int wid = tid >> 5, lane = tid & 31;
    const int g = lane >> 2, t = lane & 3;
    const int lrow  = (lane & 7) + ((lane >> 3) & 1) * 8;
    const int lcol4 = (lane >> 4) * 4;

    const __half* Qb = Q  + (size_t)bh * S_LEN * 64;
    const __half* Kb = K  + (size_t)bh * S_LEN * 64;
    const __half* Vb = Vt + (size_t)bh * 64 * S_LEN;

#define LOAD_K(st, kt) do { _Pragma("unroll") for (int i = 0; i < 4; i++) { \
    int j = tid + i * 256; int r = j >> 3, cq = j & 7;                      \
    cp16(uK[st] + (uint32_t)(r * APK + cq * 4) * 4,                         \
         Kb + (size_t)((kt) * 128 + r) * 64 + cq * 8); } } while (0)
#define LOAD_V(st, kt) do { _Pragma("unroll") for (int i = 0; i < 4; i++) { \
    int j = tid + i * 256; int r = j >> 4, cq = j & 15;                     \
    cp16(uV[st] + (uint32_t)(r * APV + cq * 4) * 4,                         \
         Vb + (size_t)r * S_LEN + (kt) * 128 + cq * 8); } } while (0)

    // prologue: Q + K0 + V0
#pragma unroll
    for (int i = 0; i < 4; i++) {
        int j = tid + i * 256; int r = j >> 3, cq = j & 7;
        cp16(uQ + (uint32_t)(r * APK + cq * 4) * 4, Qb + (size_t)(q0 + r) * 64 + cq * 8);
    }
    LOAD_K(0, 0); LOAD_V(0, 0); CP_COMMIT();
    CP_WAIT0();
    __syncthreads();

    const int rbase = wid * 16 + g;

    uint32_t qf[4][4];
#pragma unroll
    for (int ks = 0; ks < 4; ks++)
        ldsm4(qf[ks][0], qf[ks][1], qf[ks][2], qf[ks][3],
              uQ + 4u * ((wid * 16 + lrow) * APK + ks * 8 + lcol4));

    float lacc0[4] = {0.f, 0.f, 0.f, 0.f};
    float lacc1[4] = {0.f, 0.f, 0.f, 0.f};
    float oacc[8][4];
#pragma unroll
    for (int i = 0; i < 8; i++)
#pragma unroll
        for (int r = 0; r < 4; r++) oacc[i][r] = 0.f;

    for (int kt = 0; kt < 16; kt++) {
        const int st = kt & 1;
        if (kt > 0) { CP_WAIT0(); __syncthreads(); }
        if (kt < 15) { LOAD_K(st ^ 1, kt + 1); LOAD_V(st ^ 1, kt + 1); CP_COMMIT(); }

#pragma unroll
        for (int hf = 0; hf < 2; hf++) {
            float sacc[8][4];
#pragma unroll
            for (int i = 0; i < 8; i++)
#pragma unroll
                for (int r = 0; r < 4; r++) sacc[i][r] = -POFF;

#pragma unroll
            for (int ks = 0; ks < 4; ks++) {
#pragma unroll
                for (int np = 0; np < 4; np++) {
                    uint32_t r0, r1, r2, r3;
                    ldsm4(r0, r1, r2, r3,
                          uK[st] + 4u * ((hf * 64 + np * 16 + lrow) * APK + ks * 8 + lcol4));
                    mma16(sacc[2 * np],     qf[ks], r0, r2);
                    mma16(sacc[2 * np + 1], qf[ks], r1, r3);
                }
            }

#pragma unroll
            for (int ks = 0; ks < 4; ks++) {
                uint32_t pf[4];
                pf[0] = pexp2(sacc[2 * ks][0],     sacc[2 * ks][1]);
                pf[1] = pexp2(sacc[2 * ks][2],     sacc[2 * ks][3]);
                pf[2] = pexp2(sacc[2 * ks + 1][0], sacc[2 * ks + 1][1]);
                pf[3] = pexp2(sacc[2 * ks + 1][2], sacc[2 * ks + 1][3]);

                if (ks & 1) mma16(lacc1, pf, ONES2, ONES2);
                else        mma16(lacc0, pf, ONES2, ONES2);

#pragma unroll
                for (int np = 0; np < 4; np++) {
                    uint32_t r0, r1, r2, r3;
                    ldsm4(r0, r1, r2, r3,
                          uV[st] + 4u * ((np * 16 + lrow) * APV + hf * 32 + ks * 8 + lcol4));
                    mma16(oacc[2 * np],     pf, r0, r2);
                    mma16(oacc[2 * np + 1], pf, r1, r3);
                }
            }
        }
    }

    const float inv0 = 1.f / (lacc0[0] + lacc1[0]);
    const float inv1 = 1.f / (lacc0[2] + lacc1[2]);
    const int b = bh >> 4, h = bh & 15;
    const int row0 = q0 + rbase;
    __half* base0 = Ctx + ((size_t)(b * 2048 + row0)) * 1024 + h * 64;
#pragma unroll
    for (int nt = 0; nt < 8; nt++) {
        const int col = nt * 8 + 2 * t;
        *(__half2*)(base0 + col) = __floats2half2_rn(oacc[nt][0] * inv0, oacc[nt][1] * inv0);
        *(__half2*)(base0 + 8 * 1024 + col) = __floats2half2_rn(oacc[nt][2] * inv1,
                                                                oacc[nt][3] * inv1);
    }
}

// ======================= fused prep: weights transpose + x convert ========
__global__ __launch_bounds__(256) void prep_all(
    const float* __restrict__ Wq, const float* __restrict__ Wk,
    const float* __restrict__ Wv, const float* __restrict__ Wo,
    const float* __restrict__ x,
    __half* __restrict__ Wh, __half* __restrict__ Woh, __half* __restrict__ xh)
{
    const int z = blockIdx.z;
    const int tx = threadIdx.x, ty = threadIdx.y;   // 32 x 8
    if (z == 4) {
        const int tl = (blockIdx.y * 32 + blockIdx.x) * 256 + ty * 32 + tx;
#pragma unroll
        for (int k = 0; k < 4; k++) {
            const int i = tl + k * 262144;
            float4 v = ((const float4*)x)[i];
            ((__half2*)xh)[2 * i]     = __floats2half2_rn(v.x, v.y);
            ((__half2*)xh)[2 * i + 1] = __floats2half2_rn(v.z, v.w);
        }
        return;
    }
    __shared__ float tb[32][33];
    const float* src = (z == 0) ? Wq : (z == 1) ? Wk : (z == 2) ? Wv : Wo;
    __half* dst = (z < 3) ? (Wh + (size_t)z * D_MOD * D_MOD) : Woh;
    const int k0 = blockIdx.x * 32, n0 = blockIdx.y * 32;
#pragma unroll
    for (int i = 0; i < 4; i++)
        tb[ty + i * 8][tx] = src[(size_t)(k0 + ty + i * 8) * D_MOD + n0 + tx];
    __syncthreads();
#pragma unroll
    for (int i = 0; i < 4; i++)
        dst[(size_t)(n0 + ty + i * 8) * D_MOD + k0 + tx] = __float2half_rn(tb[tx][ty + i * 8]);
}

// ---------------- LayerNorm (input h already includes residual) -----------
__global__ __launch_bounds__(256) void ln_kernel(
    const float* __restrict__ hin,
    const float* __restrict__ gamma, const float* __restrict__ beta,
    float* __restrict__ out)
{
    const int row = blockIdx.x;
    const int tid = threadIdx.x;

    const float4 h = ((const float4*)(hin + (size_t)row * D_MOD))[tid];

    float sum = h.x + h.y + h.z + h.w;
    float ssq = h.x * h.x + h.y * h.y + h.z * h.z + h.w * h.w;
#pragma unroll
    for (int o = 16; o > 0; o >>= 1) {
        sum += __shfl_xor_sync(0xffffffffu, sum, o);
        ssq += __shfl_xor_sync(0xffffffffu, ssq, o);
    }
    __shared__ float rs[8], rq[8];
    const int warp = tid >> 5, lane = tid & 31;
    if (lane == 0) { rs[warp] = sum; rq[warp] = ssq; }
    __syncthreads();
    float ts = 0.f, tq = 0.f;
#pragma unroll
    for (int i = 0; i < 8; i++) { ts += rs[i]; tq += rq[i]; }

    const float mu   = ts * (1.f / (float)D_MOD);
    const float var  = tq * (1.f / (float)D_MOD) - mu * mu;
    const float rstd = rsqrtf(var + 1e-5f);

    const float4 gg = ((const float4*)gamma)[tid];
    const float4 bb = ((const float4*)beta)[tid];
    float4 o;
    o.x = (h.x - mu) * rstd * gg.x + bb.x;
    o.y = (h.y - mu) * rstd * gg.y + bb.y;
    o.z = (h.z - mu) * rstd * gg.z + bb.z;
    o.w = (h.w - mu) * rstd * gg.w + bb.w;
    ((float4*)(out + (size_t)row * D_MOD))[tid] = o;
}

// ---------------- launch ----------------------------------------------------
extern "C" void kernel_launch(void* const* d_in, const int* in_sizes, int n_in,
                              void* d_out, int out_size)
{
    const float* x  = (const float*)d_in[0];
    const float* Wq = (const float*)d_in[1];
    const float* bq = (const float*)d_in[2];
    const float* Wk = (const float*)d_in[3];
    const float* bk = (const float*)d_in[4];
    const float* Wv = (const float*)d_in[5];
    const float* bv = (const float*)d_in[6];
    const float* Wo = (const float*)d_in[7];
    const float* bo = (const float*)d_in[8];
    const float* ga = (const float*)d_in[9];
    const float* be = (const float*)d_in[10];
    float* out = (float*)d_out;

    __half *Xh, *Wh, *Woh, *Qp, *Kp, *Vtp, *Ch;
    float *Pp;
    cudaGetSymbolAddress((void**)&Xh,  g_xh);
    cudaGetSymbolAddress((void**)&Wh,  g_Wh);
    cudaGetSymbolAddress((void**)&Woh, g_Woh);
    cudaGetSymbolAddress((void**)&Qp,  g_Q);
    cudaGetSymbolAddress((void**)&Kp,  g_K);
    cudaGetSymbolAddress((void**)&Vtp, g_Vt);
    cudaGetSymbolAddress((void**)&Ch,  g_ctxh);
    cudaGetSymbolAddress((void**)&Pp,  g_prj);

    cudaFuncSetAttribute(attn_h, cudaFuncAttributeMaxDynamicSharedMemorySize, ATTN_SMEM);
    cudaFuncSetAttribute(gemm_h<1>, cudaFuncAttributeMaxDynamicSharedMemorySize, GEMM_SMEM);
    cudaFuncSetAttribute(gemm_h<0>, cudaFuncAttributeMaxDynamicSharedMemorySize, GEMM_SMEM);

    prep_all<<<dim3(32, 32, 5), dim3(32, 8)>>>(Wq, Wk, Wv, Wo, x, Wh, Woh, Xh);

    gemm_h<1><<<dim3(24, 32), 256, GEMM_SMEM>>>(Xh, Wh, bq, bk, bv, Qp, Kp, Vtp,
                                                nullptr, nullptr);

    attn_h<<<dim3(S_LEN / 128, NBH), 256, ATTN_SMEM>>>(Qp, Kp, Vtp, Ch);

    gemm_h<0><<<dim3(8, 32), 256, GEMM_SMEM>>>(Ch, Woh, bo, bo, bo,
                                               nullptr, nullptr, nullptr, x, Pp);

    ln_kernel<<<ROWS, 256>>>(Pp, ga, be, out);
}